// round 1
// baseline (speedup 1.0000x reference)
#include <cuda_runtime.h>
#include <cuda_bf16.h>
#include <math.h>

// Problem constants (GConvLSTM_Simple: N=100000, E=3200000, CIN=COUT=32)
#define MAXN 100000
#define MAXE 3200000
#define CC   32

// Scratch (device globals; no allocation allowed)
__device__ float g_P[MAXN * CC];    // X@Wx + H@Wh  (pre-aggregation features)
__device__ float g_S[MAXN * CC];    // aggregated messages
__device__ float g_deg[MAXN];
__device__ float g_dinv[MAXN];

// ---------------------------------------------------------------------------
// K0: zero scratch (deterministic per launch)
// ---------------------------------------------------------------------------
__global__ void k_zero(int n)
{
    int total = n * CC + n;  // S then deg
    for (int i = blockIdx.x * blockDim.x + threadIdx.x; i < total;
         i += gridDim.x * blockDim.x) {
        if (i < n * CC) g_S[i] = 0.0f;
        else            g_deg[i - n * CC] = 0.0f;
    }
}

// ---------------------------------------------------------------------------
// K1: P[n, :] = X[n, :] @ Wx + H[n, :] @ Wh      (warp per node, lane = out ch)
// ---------------------------------------------------------------------------
__global__ void k_linear(const float* __restrict__ X,
                         const float* __restrict__ H,
                         const float* __restrict__ Wx,
                         const float* __restrict__ Wh,
                         int n)
{
    __shared__ float sWx[CC * CC];
    __shared__ float sWh[CC * CC];
    for (int i = threadIdx.x; i < CC * CC; i += blockDim.x) {
        sWx[i] = Wx[i];
        sWh[i] = Wh[i];
    }
    __syncthreads();

    int gwarp = (blockIdx.x * blockDim.x + threadIdx.x) >> 5;
    int lane  = threadIdx.x & 31;
    if (gwarp >= n) return;

    float x = X[gwarp * CC + lane];   // coalesced 128B row load
    float h = H[gwarp * CC + lane];
    float acc = 0.0f;
#pragma unroll
    for (int k = 0; k < CC; k++) {
        float xk = __shfl_sync(0xffffffffu, x, k);
        float hk = __shfl_sync(0xffffffffu, h, k);
        acc = fmaf(xk, sWx[k * CC + lane], acc);
        acc = fmaf(hk, sWh[k * CC + lane], acc);
    }
    g_P[gwarp * CC + lane] = acc;
}

// ---------------------------------------------------------------------------
// K2: deg[dst] += w   (scalar atomics, spread over N addresses)
// ---------------------------------------------------------------------------
__global__ void k_degree(const int* __restrict__ dst,
                         const float* __restrict__ w, int e)
{
    for (int i = blockIdx.x * blockDim.x + threadIdx.x; i < e;
         i += gridDim.x * blockDim.x) {
        atomicAdd(&g_deg[dst[i]], w[i]);
    }
}

// ---------------------------------------------------------------------------
// K3: dinv = deg > 0 ? rsqrt(max(deg, 1e-12)) : 0
// ---------------------------------------------------------------------------
__global__ void k_dinv(int n)
{
    int i = blockIdx.x * blockDim.x + threadIdx.x;
    if (i < n) {
        float d = g_deg[i];
        g_dinv[i] = (d > 0.0f) ? rsqrtf(fmaxf(d, 1e-12f)) : 0.0f;
    }
}

// ---------------------------------------------------------------------------
// K4: scatter — warp per edge; lane = channel.
//     S[d, c] += dinv[s] * w * dinv[d] * P[s, c]
// ---------------------------------------------------------------------------
__global__ void k_scatter(const int* __restrict__ src,
                          const int* __restrict__ dst,
                          const float* __restrict__ w, int e)
{
    int gwarp = (blockIdx.x * blockDim.x + threadIdx.x) >> 5;
    int lane  = threadIdx.x & 31;
    if (gwarp >= e) return;

    int   s    = __ldg(&src[gwarp]);
    int   d    = __ldg(&dst[gwarp]);
    float norm = __ldg(&w[gwarp]) * __ldg(&g_dinv[s]) * __ldg(&g_dinv[d]);

    float val = norm * __ldg(&g_P[s * CC + lane]);   // 128B gather (L2-resident)
    atomicAdd(&g_S[d * CC + lane], val);             // 128B contiguous atomics
}

// ---------------------------------------------------------------------------
// K5: gate epilogue. out = [O | H_new | C_new], each N*CC floats.
// ---------------------------------------------------------------------------
__device__ __forceinline__ float sigf(float x) {
    return 1.0f / (1.0f + __expf(-x));
}

__global__ void k_gates(const float* __restrict__ C,
                        const float* __restrict__ bx,
                        const float* __restrict__ bh,
                        const float* __restrict__ b_i,
                        const float* __restrict__ b_f,
                        const float* __restrict__ b_c,
                        const float* __restrict__ b_o,
                        float* __restrict__ out, int n)
{
    int idx = blockIdx.x * blockDim.x + threadIdx.x;
    int nc  = n * CC;
    if (idx >= nc) return;
    int c = idx & (CC - 1);

    float s = g_S[idx] + bx[c] + bh[c];

    float I  = sigf(s + b_i[c]);
    float F  = sigf(s + b_f[c]);
    float T  = tanhf(s + b_c[c]);
    float Cn = F * C[idx] + I * T;
    float O  = sigf(s + b_o[c]);
    float Hn = O * tanhf(Cn);

    out[idx]          = O;
    out[nc + idx]     = Hn;
    out[2 * nc + idx] = Cn;
}

// ---------------------------------------------------------------------------
// Launcher
// Inputs (metadata order):
//  0:X [N,32] f32   1:edge_index [2,E] i32   2:edge_weight [E] f32
//  3:H [N,32] f32   4:C [N,32] f32
//  5:Wx [32,32]     6:bx [32]   7:Wh [32,32]  8:bh [32]
//  9:b_i [1,32]    10:b_f      11:b_c        12:b_o
// Output: [O | H_new | C_new]  (3*N*32 f32)
// ---------------------------------------------------------------------------
extern "C" void kernel_launch(void* const* d_in, const int* in_sizes, int n_in,
                              void* d_out, int out_size)
{
    const float* X   = (const float*)d_in[0];
    const int*   ei  = (const int*)  d_in[1];
    const float* w   = (const float*)d_in[2];
    const float* H   = (const float*)d_in[3];
    const float* C   = (const float*)d_in[4];
    const float* Wx  = (const float*)d_in[5];
    const float* bx  = (const float*)d_in[6];
    const float* Wh  = (const float*)d_in[7];
    const float* bh  = (const float*)d_in[8];
    const float* b_i = (const float*)d_in[9];
    const float* b_f = (const float*)d_in[10];
    const float* b_c = (const float*)d_in[11];
    const float* b_o = (const float*)d_in[12];
    float* out = (float*)d_out;

    const int n = in_sizes[0] / CC;   // 100000
    const int e = in_sizes[1] / 2;    // 3200000
    const int* src = ei;
    const int* dst = ei + e;

    // K0: zero S and deg
    {
        int total = n * CC + n;
        k_zero<<<(total + 511) / 512, 512>>>(n);
    }
    // K1: dense P
    {
        int threads = 256;                       // 8 warps -> 8 nodes per block
        int blocks  = (n * CC + threads - 1) / threads;
        k_linear<<<blocks, threads>>>(X, H, Wx, Wh, n);
    }
    // K2: degree
    k_degree<<<2048, 256>>>(dst, w, e);
    // K3: dinv
    k_dinv<<<(n + 255) / 256, 256>>>(n);
    // K4: scatter (warp per edge)
    {
        long long tot = (long long)e * 32;
        int threads = 256;
        int blocks  = (int)((tot + threads - 1) / threads);
        k_scatter<<<blocks, threads>>>(src, dst, w, e);
    }
    // K5: gates
    {
        int threads = 256;
        int blocks  = (n * CC + threads - 1) / threads;
        k_gates<<<blocks, threads>>>(C, bx, bh, b_i, b_f, b_c, b_o, out, n);
    }
}

// round 2
// speedup vs baseline: 2.0201x; 2.0201x over previous
#include <cuda_runtime.h>
#include <cuda_bf16.h>
#include <math.h>

// Problem constants (GConvLSTM_Simple: N=100000, E=3200000, CIN=COUT=32)
#define MAXN 100000
#define MAXE 3200000
#define CC   32

// Scratch (device globals; no allocation allowed)
__device__ float g_P[MAXN * CC];    // X@Wx + H@Wh  (pre-aggregation features)
__device__ float g_S[MAXN * CC];    // aggregated messages
__device__ float g_deg[MAXN];
__device__ float g_dinv[MAXN];

// ---------------------------------------------------------------------------
// K0: zero scratch with 128-bit stores
// ---------------------------------------------------------------------------
__global__ void k_zero(int n)
{
    int total4 = (n * CC) / 4;      // S as float4
    float4 z = make_float4(0.f, 0.f, 0.f, 0.f);
    for (int i = blockIdx.x * blockDim.x + threadIdx.x; i < total4 + n;
         i += gridDim.x * blockDim.x) {
        if (i < total4) ((float4*)g_S)[i] = z;
        else            g_deg[i - total4] = 0.0f;
    }
}

// ---------------------------------------------------------------------------
// K1: P[n, :] = X[n, :] @ Wx + H[n, :] @ Wh      (warp per node, lane = out ch)
// ---------------------------------------------------------------------------
__global__ void k_linear(const float* __restrict__ X,
                         const float* __restrict__ H,
                         const float* __restrict__ Wx,
                         const float* __restrict__ Wh,
                         int n)
{
    __shared__ float sWx[CC * CC];
    __shared__ float sWh[CC * CC];
    for (int i = threadIdx.x; i < CC * CC; i += blockDim.x) {
        sWx[i] = Wx[i];
        sWh[i] = Wh[i];
    }
    __syncthreads();

    int gwarp = (blockIdx.x * blockDim.x + threadIdx.x) >> 5;
    int lane  = threadIdx.x & 31;
    if (gwarp >= n) return;

    float x = X[gwarp * CC + lane];   // coalesced 128B row load
    float h = H[gwarp * CC + lane];
    float acc = 0.0f;
#pragma unroll
    for (int k = 0; k < CC; k++) {
        float xk = __shfl_sync(0xffffffffu, x, k);
        float hk = __shfl_sync(0xffffffffu, h, k);
        acc = fmaf(xk, sWx[k * CC + lane], acc);
        acc = fmaf(hk, sWh[k * CC + lane], acc);
    }
    g_P[gwarp * CC + lane] = acc;
}

// ---------------------------------------------------------------------------
// K2: deg[dst] += w   (scalar atomics, spread over N addresses)
// ---------------------------------------------------------------------------
__global__ void k_degree(const int* __restrict__ dst,
                         const float* __restrict__ w, int e)
{
    for (int i = blockIdx.x * blockDim.x + threadIdx.x; i < e;
         i += gridDim.x * blockDim.x) {
        atomicAdd(&g_deg[dst[i]], w[i]);
    }
}

// ---------------------------------------------------------------------------
// K3: dinv = deg > 0 ? rsqrt(max(deg, 1e-12)) : 0
// ---------------------------------------------------------------------------
__global__ void k_dinv(int n)
{
    int i = blockIdx.x * blockDim.x + threadIdx.x;
    if (i < n) {
        float d = g_deg[i];
        g_dinv[i] = (d > 0.0f) ? rsqrtf(fmaxf(d, 1e-12f)) : 0.0f;
    }
}

// ---------------------------------------------------------------------------
// K4: scatter — 8 threads per edge; each thread owns one float4 of the row.
//     S[d, c:c+4] += dinv[s] * w * dinv[d] * P[s, c:c+4]   via red.v4
// ---------------------------------------------------------------------------
__global__ void k_scatter(const int* __restrict__ src,
                          const int* __restrict__ dst,
                          const float* __restrict__ w, int e)
{
    int tid  = blockIdx.x * blockDim.x + threadIdx.x;
    int edge = tid >> 3;            // 8 threads per edge
    int sub  = tid & 7;             // float4 index within the 32-ch row
    if (edge >= e) return;

    int   s    = __ldg(&src[edge]);
    int   d    = __ldg(&dst[edge]);
    float norm = __ldg(&w[edge]) * __ldg(&g_dinv[s]) * __ldg(&g_dinv[d]);

    const float4 p = *(const float4*)&g_P[s * CC + sub * 4];  // LDG.128 (L2-res)
    float4 v;
    v.x = norm * p.x; v.y = norm * p.y; v.z = norm * p.z; v.w = norm * p.w;

    float* addr = &g_S[d * CC + sub * 4];
    asm volatile("red.global.add.v4.f32 [%0], {%1, %2, %3, %4};"
                 :: "l"(addr), "f"(v.x), "f"(v.y), "f"(v.z), "f"(v.w)
                 : "memory");
}

// ---------------------------------------------------------------------------
// K5: gate epilogue, float4-vectorized. out = [O | H_new | C_new].
// ---------------------------------------------------------------------------
__device__ __forceinline__ float sigf(float x) {
    return 1.0f / (1.0f + __expf(-x));
}

__global__ void k_gates(const float* __restrict__ C,
                        const float* __restrict__ bx,
                        const float* __restrict__ bh,
                        const float* __restrict__ b_i,
                        const float* __restrict__ b_f,
                        const float* __restrict__ b_c,
                        const float* __restrict__ b_o,
                        float* __restrict__ out, int n)
{
    int v   = blockIdx.x * blockDim.x + threadIdx.x;   // float4 index
    int nc4 = n * CC / 4;
    if (v >= nc4) return;
    int cb = (v * 4) & (CC - 1);                        // channel base (0..28)

    float4 sv = ((const float4*)g_S)[v];
    float4 cv = ((const float4*)C)[v];

    float4 ov, hv, cnv;
    float* so = &ov.x; float* sh = &hv.x; float* sc = &cnv.x;
    const float* ss = &sv.x; const float* scold = &cv.x;
#pragma unroll
    for (int j = 0; j < 4; j++) {
        int c  = cb + j;
        float s  = ss[j] + bx[c] + bh[c];
        float I  = sigf(s + b_i[c]);
        float F  = sigf(s + b_f[c]);
        float T  = tanhf(s + b_c[c]);
        float Cn = F * scold[j] + I * T;
        float O  = sigf(s + b_o[c]);
        so[j] = O;
        sh[j] = O * tanhf(Cn);
        sc[j] = Cn;
    }
    ((float4*)out)[v]           = ov;
    ((float4*)out)[nc4 + v]     = hv;
    ((float4*)out)[2 * nc4 + v] = cnv;
}

// ---------------------------------------------------------------------------
// Launcher
// Inputs (metadata order):
//  0:X [N,32] f32   1:edge_index [2,E] i32   2:edge_weight [E] f32
//  3:H [N,32] f32   4:C [N,32] f32
//  5:Wx [32,32]     6:bx [32]   7:Wh [32,32]  8:bh [32]
//  9:b_i [1,32]    10:b_f      11:b_c        12:b_o
// Output: [O | H_new | C_new]  (3*N*32 f32)
// ---------------------------------------------------------------------------
extern "C" void kernel_launch(void* const* d_in, const int* in_sizes, int n_in,
                              void* d_out, int out_size)
{
    const float* X   = (const float*)d_in[0];
    const int*   ei  = (const int*)  d_in[1];
    const float* w   = (const float*)d_in[2];
    const float* H   = (const float*)d_in[3];
    const float* C   = (const float*)d_in[4];
    const float* Wx  = (const float*)d_in[5];
    const float* bx  = (const float*)d_in[6];
    const float* Wh  = (const float*)d_in[7];
    const float* bh  = (const float*)d_in[8];
    const float* b_i = (const float*)d_in[9];
    const float* b_f = (const float*)d_in[10];
    const float* b_c = (const float*)d_in[11];
    const float* b_o = (const float*)d_in[12];
    float* out = (float*)d_out;

    const int n = in_sizes[0] / CC;   // 100000
    const int e = in_sizes[1] / 2;    // 3200000
    const int* src = ei;
    const int* dst = ei + e;

    // K0: zero S and deg
    {
        int total = n * CC / 4 + n;
        k_zero<<<(total + 511) / 512, 512>>>(n);
    }
    // K1: dense P
    {
        int threads = 256;                       // 8 warps -> 8 nodes per block
        int blocks  = (n * CC + threads - 1) / threads;
        k_linear<<<blocks, threads>>>(X, H, Wx, Wh, n);
    }
    // K2: degree
    k_degree<<<2048, 256>>>(dst, w, e);
    // K3: dinv
    k_dinv<<<(n + 255) / 256, 256>>>(n);
    // K4: scatter (8 threads per edge, red.v4)
    {
        long long tot = (long long)e * 8;
        int threads = 256;
        int blocks  = (int)((tot + threads - 1) / threads);
        k_scatter<<<blocks, threads>>>(src, dst, w, e);
    }
    // K5: gates
    {
        int nc4 = n * CC / 4;
        int threads = 256;
        int blocks  = (nc4 + threads - 1) / threads;
        k_gates<<<blocks, threads>>>(C, bx, bh, b_i, b_f, b_c, b_o, out, n);
    }
}